// round 1
// baseline (speedup 1.0000x reference)
#include <cuda_runtime.h>
#include <math_constants.h>

// Problem constants
#define NB   4
#define CIN  256
#define CI   128
#define HW   4096

// ------------------------- scratch (static __device__, no allocs) ----------
__device__ float d_theta[NB * CI * HW];          // 8 MB
__device__ float d_phi  [NB * CI * HW];          // 8 MB
__device__ float d_g    [NB * CI * HW];          // 8 MB
__device__ float d_att  [NB * CI * HW];          // 8 MB
__device__ float d_S    [(size_t)NB * HW * HW];  // 256 MB (raw S, then P in-place)
__device__ float d_m    [NB * HW];
__device__ float d_rz   [NB * HW];

// ============================================================================
// K1: theta/phi/g projections.  O[n][k][p] = sum_c W[k][c] * x[n][c][p] + b[k]
// M=128(k), N=4096(p), K=256(c). BM=128, BN=128, BK=32, 256 thr, 8x8 microtile.
// grid = (32 p-tiles, 4 n, 3 proj)
// ============================================================================
__global__ __launch_bounds__(256)
void proj_kernel(const float* __restrict__ x,
                 const float* __restrict__ tw, const float* __restrict__ tb,
                 const float* __restrict__ pw, const float* __restrict__ pb,
                 const float* __restrict__ gw, const float* __restrict__ gb)
{
    const int jt = blockIdx.x, n = blockIdx.y, pr = blockIdx.z;
    const float* W; const float* B; float* O;
    if (pr == 0)      { W = tw; B = tb; O = d_theta; }
    else if (pr == 1) { W = pw; B = pb; O = d_phi;   }
    else              { W = gw; B = gb; O = d_g;     }
    O += n * CI * HW;
    const float* X = x + (size_t)n * CIN * HW + jt * 128;

    __shared__ float As[32][128];   // [k-chunk][m]
    __shared__ float Bs[32][128];   // [k-chunk][p]

    const int tid = threadIdx.x;
    const int tx = tid % 16, ty = tid / 16;

    float acc[8][8];
    #pragma unroll
    for (int i = 0; i < 8; i++)
        #pragma unroll
        for (int j = 0; j < 8; j++) acc[i][j] = 0.f;

    for (int k0 = 0; k0 < CIN; k0 += 32) {
        // W tile (128 x 32), row-major stride CIN -> transpose into As[k][m]
        #pragma unroll
        for (int l = 0; l < 4; l++) {
            int idx = tid + l * 256;
            int row = idx >> 3, kq = idx & 7;
            float4 v = *(const float4*)(W + row * CIN + k0 + kq * 4);
            As[kq*4+0][row] = v.x; As[kq*4+1][row] = v.y;
            As[kq*4+2][row] = v.z; As[kq*4+3][row] = v.w;
        }
        // X tile (32 x 128), direct
        #pragma unroll
        for (int l = 0; l < 4; l++) {
            int idx = tid + l * 256;
            int kk = idx >> 5, pq = idx & 31;
            *(float4*)&Bs[kk][pq*4] = *(const float4*)(X + (size_t)(k0+kk) * HW + pq * 4);
        }
        __syncthreads();
        #pragma unroll
        for (int kk = 0; kk < 32; kk++) {
            float a[8], b[8];
            *(float4*)(a)   = *(float4*)&As[kk][ty*4];
            *(float4*)(a+4) = *(float4*)&As[kk][64 + ty*4];
            *(float4*)(b)   = *(float4*)&Bs[kk][tx*4];
            *(float4*)(b+4) = *(float4*)&Bs[kk][64 + tx*4];
            #pragma unroll
            for (int i = 0; i < 8; i++)
                #pragma unroll
                for (int j = 0; j < 8; j++) acc[i][j] += a[i] * b[j];
        }
        __syncthreads();
    }
    #pragma unroll
    for (int r = 0; r < 8; r++) {
        int row = (r < 4) ? (ty*4 + r) : (64 + ty*4 + r - 4);
        float bias = B[row];
        float4 o0, o1;
        o0.x = acc[r][0]+bias; o0.y = acc[r][1]+bias; o0.z = acc[r][2]+bias; o0.w = acc[r][3]+bias;
        o1.x = acc[r][4]+bias; o1.y = acc[r][5]+bias; o1.z = acc[r][6]+bias; o1.w = acc[r][7]+bias;
        *(float4*)(O + (size_t)row * HW + jt*128 + tx*4)      = o0;
        *(float4*)(O + (size_t)row * HW + jt*128 + 64 + tx*4) = o1;
    }
}

// ============================================================================
// K2: S[n][i][j] = sum_c phi[n][c][i] * theta[n][c][j]  (both K-major: TN GEMM)
// Block owns 64 i-rows, sweeps all j in tiles of 128, keeps online (m, Z).
// Stores raw S; writes d_m, d_rz at the end.  grid = (64 i-tiles, 4 n).
// ============================================================================
__global__ __launch_bounds__(256)
void s_stats_kernel()
{
    const int it = blockIdx.x, n = blockIdx.y;
    const float* PHI = d_phi   + n * CI * HW + it * 64;
    const float* THE = d_theta + n * CI * HW;
    float* S = d_S + (size_t)n * HW * HW + (size_t)(it * 64) * HW;

    __shared__ float As[32][64];     // phi chunk  [c][i]   8 KB
    __shared__ float Bs[32][128];    // theta chunk[c][j]  16 KB
    __shared__ float redm[64][16];   //  4 KB
    __shared__ float redz[64][16];   //  4 KB

    const int tid = threadIdx.x;
    const int tx = tid % 16, ty = tid / 16;

    float m_run[4], z_run[4];
    #pragma unroll
    for (int r = 0; r < 4; r++) { m_run[r] = -CUDART_INF_F; z_run[r] = 0.f; }

    for (int jt = 0; jt < 32; jt++) {
        float acc[4][8];
        #pragma unroll
        for (int r = 0; r < 4; r++)
            #pragma unroll
            for (int c = 0; c < 8; c++) acc[r][c] = 0.f;

        for (int k0 = 0; k0 < CI; k0 += 32) {
            #pragma unroll
            for (int l = 0; l < 2; l++) {
                int idx = tid + l * 256;
                int kk = idx >> 4, iq = idx & 15;
                *(float4*)&As[kk][iq*4] = *(const float4*)(PHI + (size_t)(k0+kk) * HW + iq * 4);
            }
            #pragma unroll
            for (int l = 0; l < 4; l++) {
                int idx = tid + l * 256;
                int kk = idx >> 5, jq = idx & 31;
                *(float4*)&Bs[kk][jq*4] = *(const float4*)(THE + (size_t)(k0+kk) * HW + jt*128 + jq * 4);
            }
            __syncthreads();
            #pragma unroll
            for (int kk = 0; kk < 32; kk++) {
                float a[4], b[8];
                *(float4*)(a)   = *(float4*)&As[kk][ty*4];
                *(float4*)(b)   = *(float4*)&Bs[kk][tx*4];
                *(float4*)(b+4) = *(float4*)&Bs[kk][64 + tx*4];
                #pragma unroll
                for (int r = 0; r < 4; r++)
                    #pragma unroll
                    for (int c = 0; c < 8; c++) acc[r][c] += a[r] * b[c];
            }
            __syncthreads();
        }
        // store raw S tile + online stats update
        #pragma unroll
        for (int r = 0; r < 4; r++) {
            float* Sr = S + (size_t)(ty*4 + r) * HW + jt*128;
            *(float4*)(Sr + tx*4)      = *(float4*)&acc[r][0];
            *(float4*)(Sr + 64 + tx*4) = *(float4*)&acc[r][4];
            float tmax = acc[r][0];
            #pragma unroll
            for (int c = 1; c < 8; c++) tmax = fmaxf(tmax, acc[r][c]);
            float nm = fmaxf(m_run[r], tmax);
            float zs = 0.f;
            #pragma unroll
            for (int c = 0; c < 8; c++) zs += __expf(acc[r][c] - nm);
            z_run[r] = z_run[r] * __expf(m_run[r] - nm) + zs;
            m_run[r] = nm;
        }
    }
    #pragma unroll
    for (int r = 0; r < 4; r++) {
        redm[ty*4 + r][tx] = m_run[r];
        redz[ty*4 + r][tx] = z_run[r];
    }
    __syncthreads();
    if (tid < 64) {
        float m = -CUDART_INF_F;
        #pragma unroll
        for (int t = 0; t < 16; t++) m = fmaxf(m, redm[tid][t]);
        float z = 0.f;
        #pragma unroll
        for (int t = 0; t < 16; t++) z += redz[tid][t] * __expf(redm[tid][t] - m);
        d_m [n * HW + it*64 + tid] = m;
        d_rz[n * HW + it*64 + tid] = 1.0f / z;
    }
}

// ============================================================================
// K3: P = exp(S - m_i) * rz_i, in place.  One float4 per thread, exact grid.
// ============================================================================
__global__ __launch_bounds__(256)
void softmax_apply_kernel()
{
    size_t i4 = (size_t)blockIdx.x * blockDim.x + threadIdx.x;  // float4 index
    size_t base = i4 * 4;
    size_t row = base >> 12;               // (n*HW + i)
    float m  = d_m[row];
    float rz = d_rz[row];
    float4 v = *((float4*)d_S + i4);
    v.x = __expf(v.x - m) * rz;
    v.y = __expf(v.y - m) * rz;
    v.z = __expf(v.z - m) * rz;
    v.w = __expf(v.w - m) * rz;
    *((float4*)d_S + i4) = v;
}

// ============================================================================
// K4: att[n][c][j] = sum_i g[n][c][i] * P[n][i][j]
// M=128(c), N=4096(j), K=4096(i). BM=128, BN=64, BK=32, 8x4 microtile.
// grid = (64 j-tiles, 4 n)
// ============================================================================
__global__ __launch_bounds__(256)
void att_kernel()
{
    const int jt = blockIdx.x, n = blockIdx.y;
    const float* G = d_g + n * CI * HW;
    const float* P = d_S + (size_t)n * HW * HW;
    float* O = d_att + n * CI * HW;

    __shared__ float As[32][128];  // g chunk, transposed [k][c]
    __shared__ float Bs[32][64];   // P chunk [k][j]

    const int tid = threadIdx.x;
    const int tx = tid % 16, ty = tid / 16;

    float acc[8][4];
    #pragma unroll
    for (int i = 0; i < 8; i++)
        #pragma unroll
        for (int j = 0; j < 4; j++) acc[i][j] = 0.f;

    for (int k0 = 0; k0 < HW; k0 += 32) {
        #pragma unroll
        for (int l = 0; l < 4; l++) {
            int idx = tid + l * 256;
            int row = idx >> 3, kq = idx & 7;
            float4 v = *(const float4*)(G + (size_t)row * HW + k0 + kq * 4);
            As[kq*4+0][row] = v.x; As[kq*4+1][row] = v.y;
            As[kq*4+2][row] = v.z; As[kq*4+3][row] = v.w;
        }
        #pragma unroll
        for (int l = 0; l < 2; l++) {
            int idx = tid + l * 256;
            int kk = idx >> 4, jq = idx & 15;
            *(float4*)&Bs[kk][jq*4] = *(const float4*)(P + (size_t)(k0+kk) * HW + jt*64 + jq * 4);
        }
        __syncthreads();
        #pragma unroll
        for (int kk = 0; kk < 32; kk++) {
            float a[8], b[4];
            *(float4*)(a)   = *(float4*)&As[kk][ty*4];
            *(float4*)(a+4) = *(float4*)&As[kk][64 + ty*4];
            *(float4*)(b)   = *(float4*)&Bs[kk][tx*4];
            #pragma unroll
            for (int i = 0; i < 8; i++)
                #pragma unroll
                for (int j = 0; j < 4; j++) acc[i][j] += a[i] * b[j];
        }
        __syncthreads();
    }
    #pragma unroll
    for (int r = 0; r < 8; r++) {
        int row = (r < 4) ? (ty*4 + r) : (64 + ty*4 + r - 4);
        *(float4*)(O + (size_t)row * HW + jt*64 + tx*4) = *(float4*)&acc[r][0];
    }
}

// ============================================================================
// K5: out[n][co][j] = x[n][co][j] + w_b[co] + sum_ci w_w[co][ci]*att[n][ci][j]
// M=256 (2 tiles of 128), N=4096, K=128. grid = (32 j-tiles, 2 m-tiles, 4 n)
// ============================================================================
__global__ __launch_bounds__(256)
void out_kernel(const float* __restrict__ x,
                const float* __restrict__ ww, const float* __restrict__ wb,
                float* __restrict__ out)
{
    const int jt = blockIdx.x, mt = blockIdx.y, n = blockIdx.z;
    const float* A = ww + mt * 128 * CI;
    const float* B = d_att + n * CI * HW;

    __shared__ float As[32][128];
    __shared__ float Bs[32][128];

    const int tid = threadIdx.x;
    const int tx = tid % 16, ty = tid / 16;

    float acc[8][8];
    #pragma unroll
    for (int i = 0; i < 8; i++)
        #pragma unroll
        for (int j = 0; j < 8; j++) acc[i][j] = 0.f;

    for (int k0 = 0; k0 < CI; k0 += 32) {
        #pragma unroll
        for (int l = 0; l < 4; l++) {
            int idx = tid + l * 256;
            int row = idx >> 3, kq = idx & 7;
            float4 v = *(const float4*)(A + row * CI + k0 + kq * 4);
            As[kq*4+0][row] = v.x; As[kq*4+1][row] = v.y;
            As[kq*4+2][row] = v.z; As[kq*4+3][row] = v.w;
        }
        #pragma unroll
        for (int l = 0; l < 4; l++) {
            int idx = tid + l * 256;
            int kk = idx >> 5, jq = idx & 31;
            *(float4*)&Bs[kk][jq*4] = *(const float4*)(B + (size_t)(k0+kk) * HW + jt*128 + jq * 4);
        }
        __syncthreads();
        #pragma unroll
        for (int kk = 0; kk < 32; kk++) {
            float a[8], b[8];
            *(float4*)(a)   = *(float4*)&As[kk][ty*4];
            *(float4*)(a+4) = *(float4*)&As[kk][64 + ty*4];
            *(float4*)(b)   = *(float4*)&Bs[kk][tx*4];
            *(float4*)(b+4) = *(float4*)&Bs[kk][64 + tx*4];
            #pragma unroll
            for (int i = 0; i < 8; i++)
                #pragma unroll
                for (int j = 0; j < 8; j++) acc[i][j] += a[i] * b[j];
        }
        __syncthreads();
    }
    #pragma unroll
    for (int r = 0; r < 8; r++) {
        int row = (r < 4) ? (ty*4 + r) : (64 + ty*4 + r - 4);
        int gr = mt * 128 + row;
        float bias = wb[gr];
        const float* xr = x   + (size_t)n * CIN * HW + (size_t)gr * HW + jt*128;
        float*       orow = out + (size_t)n * CIN * HW + (size_t)gr * HW + jt*128;
        float4 x0 = *(const float4*)(xr + tx*4);
        float4 x1 = *(const float4*)(xr + 64 + tx*4);
        float4 o0, o1;
        o0.x = acc[r][0]+bias+x0.x; o0.y = acc[r][1]+bias+x0.y;
        o0.z = acc[r][2]+bias+x0.z; o0.w = acc[r][3]+bias+x0.w;
        o1.x = acc[r][4]+bias+x1.x; o1.y = acc[r][5]+bias+x1.y;
        o1.z = acc[r][6]+bias+x1.z; o1.w = acc[r][7]+bias+x1.w;
        *(float4*)(orow + tx*4)      = o0;
        *(float4*)(orow + 64 + tx*4) = o1;
    }
}

// ============================================================================
extern "C" void kernel_launch(void* const* d_in, const int* in_sizes, int n_in,
                              void* d_out, int out_size)
{
    const float* x  = (const float*)d_in[0];
    const float* tw = (const float*)d_in[1];
    const float* tb = (const float*)d_in[2];
    const float* pw = (const float*)d_in[3];
    const float* pb = (const float*)d_in[4];
    const float* gw = (const float*)d_in[5];
    const float* gb = (const float*)d_in[6];
    const float* ww = (const float*)d_in[7];
    const float* wb = (const float*)d_in[8];
    float* out = (float*)d_out;

    proj_kernel<<<dim3(32, 4, 3), 256>>>(x, tw, tb, pw, pb, gw, gb);
    s_stats_kernel<<<dim3(64, 4), 256>>>();
    // 4*4096*4096 floats / 4 per thread / 256 threads = 65536 blocks (exact)
    softmax_apply_kernel<<<65536, 256>>>();
    att_kernel<<<dim3(64, 4), 256>>>();
    out_kernel<<<dim3(32, 2, 4), 256>>>(x, ww, wb, out);
}